// round 2
// baseline (speedup 1.0000x reference)
#include <cuda_runtime.h>
#include <cuda_bf16.h>
#include <cstdint>

// Problem constants (match reference)
#define N_ATOMS 200000
#define N_PAIRS 8000000
#define N_CH 4

// One thread per pair. charges: [N_ATOMS,4] f32 (float4-aligned),
// neighbor_indices: [N_PAIRS,2] i32, neighbor_distances: [N_PAIRS] f32.
// potential[i] += charges[j] * (0.5/d) ; potential[j] += charges[i] * (0.5/d)
__global__ void __launch_bounds__(256) pair_scatter_kernel(
    const float4* __restrict__ charges,     // N_ATOMS
    const int2*   __restrict__ nbr_idx,     // N_PAIRS
    const float*  __restrict__ nbr_dist,    // N_PAIRS
    float4*       __restrict__ potential)   // N_ATOMS
{
    int p = blockIdx.x * blockDim.x + threadIdx.x;
    if (p >= N_PAIRS) return;

    int2  ij = nbr_idx[p];
    float d  = nbr_dist[p];
    // EXPONENT = 1.0 -> w = d^-1 ; fold the final /2 in.
    float w  = 0.5f / d;

    float4 ci = charges[ij.x];
    float4 cj = charges[ij.y];

    float4 add_i = make_float4(cj.x * w, cj.y * w, cj.z * w, cj.w * w);
    float4 add_j = make_float4(ci.x * w, ci.y * w, ci.z * w, ci.w * w);

    float4* pi = potential + ij.x;
    float4* pj = potential + ij.y;

    // Vectorized fire-and-forget reductions: one RED.128 per atom per pair
    // instead of 4 scalar atomicAdds (sm_90+ red.global.add.v4.f32).
    asm volatile("red.global.add.v4.f32 [%0], {%1, %2, %3, %4};"
                 :: "l"(pi), "f"(add_i.x), "f"(add_i.y), "f"(add_i.z), "f"(add_i.w)
                 : "memory");
    asm volatile("red.global.add.v4.f32 [%0], {%1, %2, %3, %4};"
                 :: "l"(pj), "f"(add_j.x), "f"(add_j.y), "f"(add_j.z), "f"(add_j.w)
                 : "memory");
}

extern "C" void kernel_launch(void* const* d_in, const int* in_sizes, int n_in,
                              void* d_out, int out_size)
{
    const float4* charges  = (const float4*)d_in[0];  // N_ATOMS*4 f32
    const int2*   nbr_idx  = (const int2*)d_in[1];    // N_PAIRS*2 i32
    const float*  nbr_dist = (const float*)d_in[2];   // N_PAIRS f32
    float4*       out      = (float4*)d_out;          // N_ATOMS*4 f32

    // Output is poisoned; we accumulate, so zero it first (memset node is
    // graph-capturable).
    cudaMemsetAsync(d_out, 0, (size_t)out_size * sizeof(float));

    const int threads = 256;
    const int blocks  = (N_PAIRS + threads - 1) / threads;
    pair_scatter_kernel<<<blocks, threads>>>(charges, nbr_idx, nbr_dist, out);
}